// round 3
// baseline (speedup 1.0000x reference)
#include <cuda_runtime.h>

#define NN   80          // N (row length)
#define TPB  128         // threads per block
#define RPB  112         // rows per block (compute threads)
#define SS   113         // smem stride: 113 % 32 == 17 (odd -> conflict-free)

// dynamic smem layout (floats):
//   aBuf [NN*SS] : a[j] per row (transposed: [j*SS + rowLocal])
//   phiR [NN*SS] : phi_rev real -> overwritten with num real
//   phiI [NN*SS] : phi_rev imag -> overwritten with num imag
//   dsR  [SS]    : d_r * inv_den per row
//   dsI  [SS]    : d_i * inv_den per row
// total = (3*80*113 + 2*113)*4 = 109,312 B  -> 2 CTAs/SM

__global__ __launch_bounds__(TPB, 2)
void bk_green_kernel(const float* __restrict__ he,
                     const float* __restrict__ h0d,
                     const float* __restrict__ h0s,
                     const float* __restrict__ h0p,
                     float* __restrict__ out,
                     int Brows)
{
    extern __shared__ float sm[];
    float* aBuf = sm;
    float* phiR = sm + NN * SS;
    float* phiI = phiR + NN * SS;
    float* dsR  = phiI + NN * SS;
    float* dsI  = dsR + SS;
    __shared__ float bcBuf[NN - 1];

    const int t = threadIdx.x;
    const int rowBase = blockIdx.x * RPB;
    const int rows = min(RPB, Brows - rowBase);

    // bc[k] = h0_super[k] * h0_sub[k] (shared across all rows)
    if (t < NN - 1) bcBuf[t] = h0s[t] * h0p[t];

    // Coalesced staging: a[row][j] = he[row][j] + h0_diag[j], transposed into smem.
    for (int i = t; i < rows * NN; i += TPB) {
        int row = i / NN;
        int j = i - row * NN;
        aBuf[j * SS + row] = he[(size_t)rowBase * NN + i] + __ldg(&h0d[j]);
    }
    __syncthreads();

    if (t < rows) {
        // ---- Pass 1: reverse continuant phi_rev[0..79] into smem ----
        float pr = 1.0f, pi = 0.0f;
        float cr = aBuf[(NN - 1) * SS + t];
        float ci = -1.0f;
        phiR[0 * SS + t] = 1.0f; phiI[0 * SS + t] = 0.0f;
        phiR[1 * SS + t] = cr;   phiI[1 * SS + t] = ci;
        #pragma unroll 4
        for (int k = 1; k <= NN - 2; k++) {
            float ak = aBuf[(NN - 1 - k) * SS + t];
            float bk = bcBuf[NN - 1 - k];
            float nr = ak * cr + ci - bk * pr;
            float ni = ak * ci - cr - bk * pi;
            phiR[(k + 1) * SS + t] = nr;
            phiI[(k + 1) * SS + t] = ni;
            pr = cr; pi = ci; cr = nr; ci = ni;
        }

        // ---- Pass 2: forward continuant theta; num[k] = theta_k * phi_rev[79-k]
        //      overwrites the phi slot it reads (slot used exactly once). ----
        pr = 1.0f; pi = 0.0f;
        cr = aBuf[0 * SS + t];   // theta_1
        ci = -1.0f;
        // num[0] = theta_0 * phi_rev[79] = phi_rev[79]: already in place.
        #pragma unroll 4
        for (int k = 1; k <= NN - 1; k++) {
            int slot = (NN - 1 - k) * SS + t;
            float qr = phiR[slot], qi = phiI[slot];
            phiR[slot] = cr * qr - ci * qi;   // num_r[k]
            phiI[slot] = cr * qi + ci * qr;   // num_i[k]
            float ak = aBuf[k * SS + t];
            float bk = bcBuf[k - 1];
            float nr = ak * cr + ci - bk * pr;
            float ni = ak * ci - cr - bk * pi;
            pr = cr; pi = ci; cr = nr; ci = ni;
        }
        // (cr, ci) = theta_N = denominator
        float inv = 1.0f / (cr * cr + ci * ci);
        dsR[t] = cr * inv;
        dsI[t] = ci * inv;
    }
    __syncthreads();

    // ---- Coalesced output: out[row][j] = num[j] * (dsR - i*dsI)  (float2) ----
    float2* out2 = (float2*)out;
    for (int i = t; i < rows * NN; i += TPB) {
        int row = i / NN;
        int j = i - row * NN;
        int slot = (NN - 1 - j) * SS + row;
        float nr = phiR[slot], ni = phiI[slot];
        float dr = dsR[row], di = dsI[row];
        float2 g;
        g.x = nr * dr + ni * di;
        g.y = ni * dr - nr * di;
        out2[(size_t)rowBase * NN + i] = g;
    }
}

extern "C" void kernel_launch(void* const* d_in, const int* in_sizes, int n_in,
                              void* d_out, int out_size)
{
    const float* he  = (const float*)d_in[0];   // he_diag (B*N)
    const float* h0d = (const float*)d_in[1];   // h0_diag (N)
    const float* h0s = (const float*)d_in[2];   // h0_sub  (N-1)
    const float* h0p = (const float*)d_in[3];   // h0_super(N-1)

    int Brows = in_sizes[0] / NN;
    size_t smem = (size_t)(3 * NN * SS + 2 * SS) * sizeof(float);  // 109,312 B

    cudaFuncSetAttribute(bk_green_kernel,
                         cudaFuncAttributeMaxDynamicSharedMemorySize, (int)smem);

    int grid = (Brows + RPB - 1) / RPB;
    bk_green_kernel<<<grid, TPB, smem>>>(he, h0d, h0s, h0p, (float*)d_out, Brows);
}

// round 4
// speedup vs baseline: 1.8259x; 1.8259x over previous
#include <cuda_runtime.h>

#define NN  80          // row length N
#define G   8           // threads per row
#define C   10          // recursion steps per thread (G*C == NN)
#define TPB 256
#define RPC (TPB / G)   // rows per CTA = 32

// One transfer-matrix step: s = (x(top), y(bottom)) complex;
// new_top = (a - i)*x - b*y ; new_bottom = x.
__device__ __forceinline__ void mstep(float a, float b,
                                      float& xr, float& xi, float& yr, float& yi)
{
    float nr = a * xr + xi - b * yr;
    float ni = a * xi - xr - b * yi;
    yr = xr; yi = xi;
    xr = nr; xi = ni;
}

// 2x2 complex matmul C = A*B. Layout: {00r,00i,01r,01i,10r,10i,11r,11i}
__device__ __forceinline__ void mmul(const float* A, const float* B, float* Cm)
{
    Cm[0] = A[0]*B[0] - A[1]*B[1] + A[2]*B[4] - A[3]*B[5];
    Cm[1] = A[0]*B[1] + A[1]*B[0] + A[2]*B[5] + A[3]*B[4];
    Cm[2] = A[0]*B[2] - A[1]*B[3] + A[2]*B[6] - A[3]*B[7];
    Cm[3] = A[0]*B[3] + A[1]*B[2] + A[2]*B[7] + A[3]*B[6];
    Cm[4] = A[4]*B[0] - A[5]*B[1] + A[6]*B[4] - A[7]*B[5];
    Cm[5] = A[4]*B[1] + A[5]*B[0] + A[6]*B[5] + A[7]*B[4];
    Cm[6] = A[4]*B[2] - A[5]*B[3] + A[6]*B[6] - A[7]*B[7];
    Cm[7] = A[4]*B[3] + A[5]*B[2] + A[6]*B[7] + A[7]*B[6];
}

__global__ __launch_bounds__(TPB, 2)
void bk_green_scan_kernel(const float* __restrict__ he,
                          const float* __restrict__ h0d,
                          const float* __restrict__ h0s,
                          const float* __restrict__ h0p,
                          float* __restrict__ out,
                          int Brows)
{
    // bthS[k] = beta for forward theta step k  (bc[k-1], bthS[0]=0)
    // bcS[m]  = bc[m] with bcS[79]=0 (used as beta for phi step via index 79-m)
    __shared__ float bthS[NN];
    __shared__ float bcS[NN];

    const int tid  = threadIdx.x;
    const int lane = tid & 31;
    const int l    = lane & (G - 1);           // lane within 8-thread row group
    const int row  = blockIdx.x * RPC + (tid >> 3);
    const unsigned mask = 0xffffffffu;

    if (tid < NN) {
        float bcv = (tid <= NN - 2) ? h0s[tid] * h0p[tid] : 0.0f;
        bcS[tid]  = bcv;
        bthS[tid] = (tid == 0) ? 0.0f : h0s[tid - 1] * h0p[tid - 1];
    }
    __syncthreads();

    const int rowc = min(row, Brows - 1);
    const int j0 = C * l;                      // this thread's theta chunk start

    // ---- load own a-chunk: a[j0 .. j0+9] ----
    float a_reg[C];
    {
        const float* hrow = he + (size_t)rowc * NN + j0;
        #pragma unroll
        for (int r = 0; r < C; r++)
            a_reg[r] = __ldg(hrow + r) + __ldg(h0d + j0 + r);
    }

    // ---- build chunk transfer products (theta and mirrored phi), 2 columns each ----
    // theta chunk: steps k = j0..j0+9, coef a_reg[r], beta bthS[j0+r]
    // phi chunk (mirrored: lane l owns phi_rev indices m0..m0+9, m0 = C*(G-1-l)):
    //   step m = m0+r uses coef a_reg[9-r], beta bcS[j0 + 9-r]
    float tur = 1.f, tui = 0.f, tvr = 0.f, tvi = 0.f;   // theta col0 top / ...
    float tyr = 0.f, tyi = 0.f, twr = 1.f, twi = 0.f;   // bottoms: col0 bot=0, col1: top=0,bot=1
    float pur = 1.f, pui = 0.f, pvr = 0.f, pvi = 0.f;
    float pyr = 0.f, pyi = 0.f, pwr = 1.f, pwi = 0.f;
    #pragma unroll
    for (int r = 0; r < C; r++) {
        float at = a_reg[r],      bt = bthS[j0 + r];
        float ap = a_reg[C-1-r],  bp = bcS[j0 + C - 1 - r];
        mstep(at, bt, tur, tui, tyr, tyi);   // theta col0
        mstep(at, bt, tvr, tvi, twr, twi);   // theta col1
        mstep(ap, bp, pur, pui, pyr, pyi);   // phi col0
        mstep(ap, bp, pvr, pvi, pwr, pwi);   // phi col1
    }

    // ---- theta scan (ascending lanes): J_l = P_l * P_{l-1} * ... * P_0 ----
    float sxr, sxi, syr, syi;   // prefix state for theta replay
    {
        float J[8] = { tur, tui, tvr, tvi, tyr, tyi, twr, twi };
        #pragma unroll
        for (int d = 1; d < G; d <<= 1) {
            float T[8], R[8];
            #pragma unroll
            for (int i = 0; i < 8; i++) T[i] = __shfl_up_sync(mask, J[i], d, G);
            mmul(J, T, R);
            bool use = (l >= d);
            #pragma unroll
            for (int i = 0; i < 8; i++) J[i] = use ? R[i] : J[i];
        }
        // prefix = first column of J from lane l-1 ; lane 0 = identity
        float q0 = __shfl_up_sync(mask, J[0], 1, G);
        float q1 = __shfl_up_sync(mask, J[1], 1, G);
        float q4 = __shfl_up_sync(mask, J[4], 1, G);
        float q5 = __shfl_up_sync(mask, J[5], 1, G);
        sxr = (l == 0) ? 1.f : q0;
        sxi = (l == 0) ? 0.f : q1;
        syr = (l == 0) ? 0.f : q4;
        syi = (l == 0) ? 0.f : q5;
    }

    // ---- phi scan (descending lanes): J'_l = P'_l * P'_{l+1} * ... * P'_{G-1} ----
    float pxr, pxi, qyr, qyi;   // prefix state for phi replay
    {
        float J[8] = { pur, pui, pvr, pvi, pyr, pyi, pwr, pwi };
        #pragma unroll
        for (int d = 1; d < G; d <<= 1) {
            float T[8], R[8];
            #pragma unroll
            for (int i = 0; i < 8; i++) T[i] = __shfl_down_sync(mask, J[i], d, G);
            mmul(J, T, R);
            bool use = (l <= G - 1 - d);
            #pragma unroll
            for (int i = 0; i < 8; i++) J[i] = use ? R[i] : J[i];
        }
        float q0 = __shfl_down_sync(mask, J[0], 1, G);
        float q1 = __shfl_down_sync(mask, J[1], 1, G);
        float q4 = __shfl_down_sync(mask, J[4], 1, G);
        float q5 = __shfl_down_sync(mask, J[5], 1, G);
        pxr = (l == G - 1) ? 1.f : q0;
        pxi = (l == G - 1) ? 0.f : q1;
        qyr = (l == G - 1) ? 0.f : q4;
        qyi = (l == G - 1) ? 0.f : q5;
    }

    // ---- replay: theta_{j0+r} and phi_rev_{m0+r}, interleaved for ILP ----
    float thr[C], thi[C], phr[C], phi_[C];
    #pragma unroll
    for (int r = 0; r < C; r++) {
        thr[r] = sxr; thi[r] = sxi;          // theta_{j0+r}
        phr[r] = pxr; phi_[r] = pxi;         // phi_rev_{m0+r}
        float at = a_reg[r],      bt = bthS[j0 + r];
        float ap = a_reg[C-1-r],  bp = bcS[j0 + C - 1 - r];
        mstep(at, bt, sxr, sxi, syr, syi);
        mstep(ap, bp, pxr, pxi, qyr, qyi);
    }
    // lane 7's final theta top = theta_N (denominator)
    float dr = __shfl_sync(mask, sxr, G - 1, G);
    float di = __shfl_sync(mask, sxi, G - 1, G);
    float inv = 1.0f / (dr * dr + di * di);
    float cdr = dr * inv, cdi = di * inv;

    // ---- num_j = theta_j * phi_rev_{N-1-j} ; j = j0+r -> local phi slot (9-r) ----
    if (row < Brows) {
        float4* out4 = (float4*)out;
        size_t base = (size_t)row * (NN / 2) * 4 + (size_t)l * (C / 2) * 4; // row*160 + l*20 f4? no:
        // out is (B, N, 2) floats; float4 index = (row*NN + j0)*2/4 = row*40 + 5*l
        base = (size_t)row * 40 + (size_t)l * 5;
        #pragma unroll
        for (int n = 0; n < C / 2; n++) {
            int r0 = 2 * n, r1 = 2 * n + 1;
            float n0r = thr[r0] * phr[C-1-r0] - thi[r0] * phi_[C-1-r0];
            float n0i = thr[r0] * phi_[C-1-r0] + thi[r0] * phr[C-1-r0];
            float n1r = thr[r1] * phr[C-1-r1] - thi[r1] * phi_[C-1-r1];
            float n1i = thr[r1] * phi_[C-1-r1] + thi[r1] * phr[C-1-r1];
            float4 g;
            g.x = n0r * cdr + n0i * cdi;
            g.y = n0i * cdr - n0r * cdi;
            g.z = n1r * cdr + n1i * cdi;
            g.w = n1i * cdr - n1r * cdi;
            out4[base + n] = g;
        }
    }
}

extern "C" void kernel_launch(void* const* d_in, const int* in_sizes, int n_in,
                              void* d_out, int out_size)
{
    const float* he  = (const float*)d_in[0];   // he_diag (B*N)
    const float* h0d = (const float*)d_in[1];   // h0_diag (N)
    const float* h0s = (const float*)d_in[2];   // h0_sub  (N-1)
    const float* h0p = (const float*)d_in[3];   // h0_super(N-1)

    int Brows = in_sizes[0] / NN;
    int grid = (Brows + RPC - 1) / RPC;
    bk_green_scan_kernel<<<grid, TPB>>>(he, h0d, h0s, h0p, (float*)d_out, Brows);
}

// round 5
// speedup vs baseline: 2.1953x; 1.2023x over previous
#include <cuda_runtime.h>

#define NN  80          // row length N
#define G   4           // threads per row
#define C   20          // recursion steps per thread (G*C == NN)
#define TPB 256
#define RPC (TPB / G)   // rows per CTA = 64

// One transfer-matrix step: new_top = (a - i)*x - b*y ; new_bottom = x.
__device__ __forceinline__ void mstep(float a, float b,
                                      float& xr, float& xi, float& yr, float& yi)
{
    float nr = a * xr + xi - b * yr;
    float ni = a * xi - xr - b * yi;
    yr = xr; yi = xi;
    xr = nr; xi = ni;
}

// 2x2 complex matmul C = A*B. Layout: {00r,00i,01r,01i,10r,10i,11r,11i}
__device__ __forceinline__ void mmul(const float* A, const float* B, float* Cm)
{
    Cm[0] = A[0]*B[0] - A[1]*B[1] + A[2]*B[4] - A[3]*B[5];
    Cm[1] = A[0]*B[1] + A[1]*B[0] + A[2]*B[5] + A[3]*B[4];
    Cm[2] = A[0]*B[2] - A[1]*B[3] + A[2]*B[6] - A[3]*B[7];
    Cm[3] = A[0]*B[3] + A[1]*B[2] + A[2]*B[7] + A[3]*B[6];
    Cm[4] = A[4]*B[0] - A[5]*B[1] + A[6]*B[4] - A[7]*B[5];
    Cm[5] = A[4]*B[1] + A[5]*B[0] + A[6]*B[5] + A[7]*B[4];
    Cm[6] = A[4]*B[2] - A[5]*B[3] + A[6]*B[6] - A[7]*B[7];
    Cm[7] = A[4]*B[3] + A[5]*B[2] + A[6]*B[7] + A[7]*B[6];
}

__global__ __launch_bounds__(TPB, 2)
void bk_green_scan4_kernel(const float* __restrict__ he,
                           const float* __restrict__ h0d,
                           const float* __restrict__ h0s,
                           const float* __restrict__ h0p,
                           float* __restrict__ out,
                           int Brows)
{
    // bthS[k] = beta for forward theta step k (= bc[k-1], bthS[0]=0)
    // bcS[m]  = bc[m], bcS[79] = 0 (phi beta accessed via reversed index)
    __shared__ float bthS[NN];
    __shared__ float bcS[NN];

    const int tid = threadIdx.x;
    const int l   = tid & (G - 1);            // lane within 4-thread row group
    const int row = blockIdx.x * RPC + (tid >> 2);
    const unsigned mask = 0xffffffffu;

    if (tid < NN) {
        bcS[tid]  = (tid <= NN - 2) ? h0s[tid] * h0p[tid] : 0.0f;
        bthS[tid] = (tid == 0) ? 0.0f : h0s[tid - 1] * h0p[tid - 1];
    }
    __syncthreads();

    const int rowc = min(row, Brows - 1);
    const int j0 = C * l;                     // theta chunk start

    // ---- load own a-chunk via float4 (80B-aligned) ----
    float a_reg[C];
    {
        const float4* h4 = (const float4*)(he + (size_t)rowc * NN + j0);
        const float4* d4 = (const float4*)(h0d + j0);
        #pragma unroll
        for (int q = 0; q < C / 4; q++) {
            float4 hv = __ldg(h4 + q);
            float4 dv = __ldg(d4 + q);
            a_reg[4*q + 0] = hv.x + dv.x;
            a_reg[4*q + 1] = hv.y + dv.y;
            a_reg[4*q + 2] = hv.z + dv.z;
            a_reg[4*q + 3] = hv.w + dv.w;
        }
    }

    // ---- build chunk transfer products (theta and mirrored phi), 2 columns each ----
    // theta chunk: step k=j0+r: coef a_reg[r], beta bthS[j0+r]
    // phi chunk (lane l owns phi_rev indices m0..m0+C-1, m0 = C*(G-1-l)):
    //   step r uses coef a_reg[C-1-r], beta bcS[j0+C-1-r]
    float tur = 1.f, tui = 0.f, tvr = 0.f, tvi = 0.f;
    float tyr = 0.f, tyi = 0.f, twr = 1.f, twi = 0.f;
    float pur = 1.f, pui = 0.f, pvr = 0.f, pvi = 0.f;
    float pyr = 0.f, pyi = 0.f, pwr = 1.f, pwi = 0.f;
    #pragma unroll
    for (int r = 0; r < C; r++) {
        float at = a_reg[r],       bt = bthS[j0 + r];
        float ap = a_reg[C-1-r],   bp = bcS[j0 + C - 1 - r];
        mstep(at, bt, tur, tui, tyr, tyi);
        mstep(at, bt, tvr, tvi, twr, twi);
        mstep(ap, bp, pur, pui, pyr, pyi);
        mstep(ap, bp, pvr, pvi, pwr, pwi);
    }

    // ---- theta scan (ascending lanes, 2 rounds) ----
    float sxr, sxi, syr, syi;     // exclusive prefix for replay
    float cdr, cdi;               // conj(theta_N)/|theta_N|^2 pieces
    {
        float J[8] = { tur, tui, tvr, tvi, tyr, tyi, twr, twi };
        #pragma unroll
        for (int d = 1; d < G; d <<= 1) {
            float T[8], R[8];
            #pragma unroll
            for (int i = 0; i < 8; i++) T[i] = __shfl_up_sync(mask, J[i], d, G);
            mmul(J, T, R);
            bool use = (l >= d);
            #pragma unroll
            for (int i = 0; i < 8; i++) J[i] = use ? R[i] : J[i];
        }
        // denominator: lane G-1 inclusive product applied to init (1,0):
        // theta_N = J00 of lane G-1
        float dr = __shfl_sync(mask, J[0], G - 1, G);
        float di = __shfl_sync(mask, J[1], G - 1, G);
        float inv = 1.0f / (dr * dr + di * di);
        cdr = dr * inv; cdi = di * inv;
        // exclusive prefix state = first column of lane l-1's inclusive product
        float q0 = __shfl_up_sync(mask, J[0], 1, G);
        float q1 = __shfl_up_sync(mask, J[1], 1, G);
        float q4 = __shfl_up_sync(mask, J[4], 1, G);
        float q5 = __shfl_up_sync(mask, J[5], 1, G);
        sxr = (l == 0) ? 1.f : q0;
        sxi = (l == 0) ? 0.f : q1;
        syr = (l == 0) ? 0.f : q4;
        syi = (l == 0) ? 0.f : q5;
    }

    // ---- phi scan (descending lanes, 2 rounds) ----
    float pxr, pxi, qyr, qyi;
    {
        float J[8] = { pur, pui, pvr, pvi, pyr, pyi, pwr, pwi };
        #pragma unroll
        for (int d = 1; d < G; d <<= 1) {
            float T[8], R[8];
            #pragma unroll
            for (int i = 0; i < 8; i++) T[i] = __shfl_down_sync(mask, J[i], d, G);
            mmul(J, T, R);
            bool use = (l <= G - 1 - d);
            #pragma unroll
            for (int i = 0; i < 8; i++) J[i] = use ? R[i] : J[i];
        }
        float q0 = __shfl_down_sync(mask, J[0], 1, G);
        float q1 = __shfl_down_sync(mask, J[1], 1, G);
        float q4 = __shfl_down_sync(mask, J[4], 1, G);
        float q5 = __shfl_down_sync(mask, J[5], 1, G);
        pxr = (l == G - 1) ? 1.f : q0;
        pxi = (l == G - 1) ? 0.f : q1;
        qyr = (l == G - 1) ? 0.f : q4;
        qyi = (l == G - 1) ? 0.f : q5;
    }

    // ---- phi replay into registers ----
    float phr[C], phi_[C];
    #pragma unroll
    for (int r = 0; r < C; r++) {
        phr[r] = pxr; phi_[r] = pxi;          // phi_rev_{m0+r}
        float ap = a_reg[C-1-r], bp = bcS[j0 + C - 1 - r];
        mstep(ap, bp, pxr, pxi, qyr, qyi);
    }

    // ---- theta replay fused with num + output ----
    // j = j0+r ; num_j = theta_j * phi_rev_{79-j}, local phi slot = C-1-r.
    if (row < Brows) {
        float4* out4 = (float4*)out;          // out is (B, N, 2) floats
        size_t base = (size_t)row * (NN / 2) + (size_t)l * (C / 2);
        float gx = 0.f, gy = 0.f;
        #pragma unroll
        for (int r = 0; r < C; r++) {
            float qr = phr[C-1-r], qi = phi_[C-1-r];
            float nr = sxr * qr - sxi * qi;
            float ni = sxr * qi + sxi * qr;
            float g0 = nr * cdr + ni * cdi;
            float g1 = ni * cdr - nr * cdi;
            if ((r & 1) == 0) { gx = g0; gy = g1; }
            else {
                float4 g; g.x = gx; g.y = gy; g.z = g0; g.w = g1;
                out4[base + (r >> 1)] = g;
            }
            float at = a_reg[r], bt = bthS[j0 + r];
            mstep(at, bt, sxr, sxi, syr, syi);
        }
    }
}

extern "C" void kernel_launch(void* const* d_in, const int* in_sizes, int n_in,
                              void* d_out, int out_size)
{
    const float* he  = (const float*)d_in[0];   // he_diag (B*N)
    const float* h0d = (const float*)d_in[1];   // h0_diag (N)
    const float* h0s = (const float*)d_in[2];   // h0_sub  (N-1)
    const float* h0p = (const float*)d_in[3];   // h0_super(N-1)

    int Brows = in_sizes[0] / NN;
    int grid = (Brows + RPC - 1) / RPC;
    bk_green_scan4_kernel<<<grid, TPB>>>(he, h0d, h0s, h0p, (float*)d_out, Brows);
}